// round 14
// baseline (speedup 1.0000x reference)
#include <cuda_runtime.h>
#include <cuda_bf16.h>
#include <cstdint>

#define BATCH 16384
#define EMBED 256
#define NS    4096
#define VOCAB 50000

// smem: A 4 k-chunks x [128r x 64k bf16] XOR-swizzled = 65536
//       B 3 bufs x [128n x 64k bf16] swizzled = 49152
#define OFF_A   0
#define OFF_B   65536
#define OFF_RED 114688
#define SMEM_TOTAL 115712
#define NCH 64     // (NS/2)/128 n-tiles * 4 k-chunks
#define GEMM_CTAS 256
#define TRUE_CTAS 40
#define TRUE_WARPS (TRUE_CTAS * 8)
#define RED_BLOCKS 48   // 3*BATCH floats / 4 / 256

// ---------------- device scratch ----------------
__device__ __align__(16) __nv_bfloat16 g_Bw[NS * EMBED];
__device__ float g_c[NS];
__device__ __align__(16) float g_sum[3][BATCH];   // [0],[1]: N-halves; [2]: true
__device__ double g_part[RED_BLOCKS];
__device__ unsigned g_cnt;                         // wraps to 0 every replay

__device__ __forceinline__ float neg_log_ec(float fid) {
    const float inv_logv = 1.0f / logf((float)VOCAB + 1.0f);
    float p  = (logf(fid + 2.0f) - logf(fid + 1.0f)) * inv_logv;
    float ec = -expm1f((float)NS * log1pf(-p));
    return -logf(ec);
}

__device__ __forceinline__ unsigned su32(const void* p) {
    return (unsigned)__cvta_generic_to_shared(p);
}

__device__ __forceinline__ uint4 cvt8bf(float4 x, float4 y) {
    __align__(16) __nv_bfloat162 p[4];
    p[0] = __floats2bfloat162_rn(x.x, x.y);
    p[1] = __floats2bfloat162_rn(x.z, x.w);
    p[2] = __floats2bfloat162_rn(y.x, y.y);
    p[3] = __floats2bfloat162_rn(y.z, y.w);
    return *(const uint4*)p;
}

// ---------------- prep: gather B (bf16, MLP=4) + offsets c ----------------
// blocks [0,128): gather, 4 independent granules per thread
// blocks [128,144): c offsets
__global__ void k_pre(const int* __restrict__ sids, const float* __restrict__ W,
                      const float* __restrict__ bias) {
    const int b   = blockIdx.x;
    const int tid = threadIdx.x;
    if (b < 128) {
        int i0 = b * 256 + tid;
        int s[4], d8[4], id[4];
        #pragma unroll
        for (int j = 0; j < 4; j++) {
            int i = i0 + j * 32768;
            s[j]  = i >> 5;
            d8[j] = (i & 31) << 3;
            id[j] = sids[s[j]];
        }
        float4 x[4], y[4];
        #pragma unroll
        for (int j = 0; j < 4; j++) {
            const float4* src = (const float4*)(W + (size_t)id[j] * EMBED + d8[j]);
            x[j] = src[0];
            y[j] = src[1];
        }
        #pragma unroll
        for (int j = 0; j < 4; j++)
            *(uint4*)(g_Bw + (size_t)s[j] * EMBED + d8[j]) = cvt8bf(x[j], y[j]);
    } else {
        int s  = (b - 128) * 256 + tid;
        int id = sids[s];
        g_c[s] = bias[id] + neg_log_ec((float)id);
    }
}

// ---------------- fused GEMM + softplus + shadow true-logits ----------------
__global__ __launch_bounds__(256, 2) void k_gemm(
    const float* __restrict__ emb, const int* __restrict__ tgt,
    const float* __restrict__ W, const float* __restrict__ bias) {
    extern __shared__ __align__(16) char smp[];

    const int tid  = threadIdx.x;
    const int lane = tid & 31;
    const int warp = tid >> 5;

    // ---- shadow CTAs: true logits, hidden under the GEMM ----
    if (blockIdx.x >= GEMM_CTAS) {
        const int gw = (blockIdx.x - GEMM_CTAS) * 8 + warp;
        for (int r0 = gw * 4; r0 < BATCH; r0 += TRUE_WARPS * 4) {
            int ids[4];
            #pragma unroll
            for (int j = 0; j < 4; j++) ids[j] = tgt[r0 + j];
            float s[4];
            #pragma unroll
            for (int j = 0; j < 4; j++) {
                const float4* e4 = (const float4*)(emb + (size_t)(r0 + j) * EMBED);
                const float4* w4 = (const float4*)(W + (size_t)ids[j] * EMBED);
                float4 a0 = e4[lane], a1 = e4[lane + 32];
                float4 b0 = w4[lane], b1 = w4[lane + 32];
                s[j] = a0.x*b0.x + a0.y*b0.y + a0.z*b0.z + a0.w*b0.w
                     + a1.x*b1.x + a1.y*b1.y + a1.z*b1.z + a1.w*b1.w;
            }
            #pragma unroll
            for (int off = 16; off > 0; off >>= 1)
                #pragma unroll
                for (int j = 0; j < 4; j++)
                    s[j] += __shfl_xor_sync(0xffffffffu, s[j], off);
            if (lane == 0) {
                #pragma unroll
                for (int j = 0; j < 4; j++) {
                    float tl = s[j] + bias[ids[j]] + neg_log_ec((float)ids[j]);
                    g_sum[2][r0 + j] = fmaxf(tl, 0.f) - tl + log1pf(expf(-fabsf(tl)));
                }
            }
        }
        return;
    }

    // ---- GEMM CTAs (round-7/10 proven path) ----
    const uint32_t base = su32(smp);
    float* red = (float*)(smp + OFF_RED);
    const int wm   = warp & 3;   // 32-row group
    const int wn   = warp >> 2;  // 64-col group
    const int mb   = blockIdx.x >> 1;
    const int half = blockIdx.x & 1;
    const int m0   = mb * 128;
    const int nb0  = half * (NS / 2);

    auto loadB = [&](int ch) {
        const int nt = ch >> 2, kb = ch & 3, b = ch % 3;
        const __nv_bfloat16* sb = g_Bw + (size_t)(nb0 + nt * 128) * EMBED + kb * 64;
        #pragma unroll
        for (int it = 0; it < 4; it++) {
            int q = tid + it * 256;
            int n = q >> 3, g = q & 7;
            uint32_t dst = base + OFF_B + b * 16384 + n * 128 + (((g ^ n) & 7) << 4);
            const void* src = sb + (size_t)n * EMBED + g * 8;
            asm volatile("cp.async.cg.shared.global [%0], [%1], 16;" :: "r"(dst), "l"(src));
        }
        asm volatile("cp.async.commit_group;");
    };

    loadB(0);
    loadB(1);

    #pragma unroll 4
    for (int it = 0; it < 16; it++) {
        int idx = tid + it * 256;
        int r = idx >> 5, G = idx & 31;
        int c = G >> 3, g = G & 7;
        const float4* s = (const float4*)(emb + (size_t)(m0 + r) * EMBED + G * 8);
        float4 x = s[0], y = s[1];
        *(uint4*)(smp + OFF_A + c * 16384 + r * 128 + (((g ^ r) & 7) << 4)) = cvt8bf(x, y);
    }

    float acc[2][8][4];
    #pragma unroll
    for (int mi = 0; mi < 2; mi++)
        #pragma unroll
        for (int ni = 0; ni < 8; ni++)
            #pragma unroll
            for (int q = 0; q < 4; q++) acc[mi][ni][q] = 0.0f;
    float rs[4] = {0.f, 0.f, 0.f, 0.f};

    auto ldA = [&](unsigned (&a)[2][4], uint32_t abase, int kk) {
        #pragma unroll
        for (int mi = 0; mi < 2; mi++) {
            int rr = wm * 32 + mi * 16 + (lane & 15);
            int gp = (kk >> 3) + (lane >> 4);
            unsigned addr = abase + rr * 128 + (((gp ^ rr) & 7) << 4);
            asm volatile("ldmatrix.sync.aligned.m8n8.x4.shared.b16 {%0,%1,%2,%3}, [%4];\n"
                : "=r"(a[mi][0]), "=r"(a[mi][1]), "=r"(a[mi][2]), "=r"(a[mi][3])
                : "r"(addr));
        }
    };
    auto ldBf = [&](unsigned (&b)[8][2], uint32_t bbase, int kk) {
        #pragma unroll
        for (int np = 0; np < 4; np++) {
            int nn = wn * 64 + np * 16 + ((lane >> 4) << 3) + (lane & 7);
            int gp = (kk >> 3) + ((lane >> 3) & 1);
            unsigned addr = bbase + nn * 128 + (((gp ^ nn) & 7) << 4);
            asm volatile("ldmatrix.sync.aligned.m8n8.x4.shared.b16 {%0,%1,%2,%3}, [%4];\n"
                : "=r"(b[np * 2][0]), "=r"(b[np * 2][1]),
                  "=r"(b[np * 2 + 1][0]), "=r"(b[np * 2 + 1][1])
                : "r"(addr));
        }
    };

    for (int ch = 0; ch < NCH; ch++) {
        if (ch < NCH - 1) asm volatile("cp.async.wait_group 1;");
        else              asm volatile("cp.async.wait_group 0;");
        __syncthreads();
        if (ch + 2 < NCH) loadB(ch + 2);

        const int kb = ch & 3;
        const uint32_t abase = base + OFF_A + kb * 16384;
        const uint32_t bbase = base + OFF_B + (ch % 3) * 16384;

        unsigned aF[2][2][4];
        unsigned bF[8][2];
        ldA(aF[0], abase, 0);

        #pragma unroll
        for (int ki = 0; ki < 4; ki++) {
            ldBf(bF, bbase, ki * 16);
            if (ki < 3) ldA(aF[(ki + 1) & 1], abase, (ki + 1) * 16);
            unsigned (&a)[2][4] = aF[ki & 1];
            #pragma unroll
            for (int mi = 0; mi < 2; mi++)
                #pragma unroll
                for (int ni = 0; ni < 8; ni++)
                    asm volatile(
                        "mma.sync.aligned.m16n8k16.row.col.f32.bf16.bf16.f32 "
                        "{%0,%1,%2,%3},{%4,%5,%6,%7},{%8,%9},{%0,%1,%2,%3};\n"
                        : "+f"(acc[mi][ni][0]), "+f"(acc[mi][ni][1]),
                          "+f"(acc[mi][ni][2]), "+f"(acc[mi][ni][3])
                        : "r"(a[mi][0]), "r"(a[mi][1]), "r"(a[mi][2]), "r"(a[mi][3]),
                          "r"(bF[ni][0]), "r"(bF[ni][1]));
        }

        if (kb == 3) {
            const int nt = ch >> 2;
            const float* cp = g_c + nb0 + nt * 128 + wn * 64 + (lane & 3) * 2;
            #pragma unroll
            for (int mi = 0; mi < 2; mi++) {
                float lin0 = 0.f, lin1 = 0.f, pr0 = 1.f, pr1 = 1.f;
                #pragma unroll
                for (int ni = 0; ni < 8; ni++) {
                    float2 cf = *(const float2*)(cp + ni * 8);
                    float l0 = acc[mi][ni][0] + cf.x;
                    float l1 = acc[mi][ni][1] + cf.y;
                    float l2 = acc[mi][ni][2] + cf.x;
                    float l3 = acc[mi][ni][3] + cf.y;
                    lin0 += fmaxf(l0, 0.f) + fmaxf(l1, 0.f);
                    lin1 += fmaxf(l2, 0.f) + fmaxf(l3, 0.f);
                    pr0 *= (1.f + __expf(-fabsf(l0))) * (1.f + __expf(-fabsf(l1)));
                    pr1 *= (1.f + __expf(-fabsf(l2))) * (1.f + __expf(-fabsf(l3)));
                    acc[mi][ni][0] = 0.f; acc[mi][ni][1] = 0.f;
                    acc[mi][ni][2] = 0.f; acc[mi][ni][3] = 0.f;
                }
                rs[mi * 2 + 0] += lin0 + __logf(pr0);
                rs[mi * 2 + 1] += lin1 + __logf(pr1);
            }
        }
    }

    // ---- row-sum reduction ----
    #pragma unroll
    for (int s = 0; s < 4; s++) {
        rs[s] += __shfl_xor_sync(0xffffffffu, rs[s], 1);
        rs[s] += __shfl_xor_sync(0xffffffffu, rs[s], 2);
    }
    __syncthreads();
    if ((lane & 3) == 0) {
        #pragma unroll
        for (int s = 0; s < 4; s++) {
            int mi = s >> 1, hi = s & 1;
            int row = wm * 32 + mi * 16 + hi * 8 + (lane >> 2);
            red[wn * 128 + row] = rs[s];
        }
    }
    __syncthreads();
    if (tid < 128)
        g_sum[half][m0 + tid] = red[tid] + red[128 + tid];
}

// ---------------- fused reduction: 48 blocks; last block writes the mean ----
__global__ void k_red(float* __restrict__ out) {
    __shared__ double wsum[8];
    __shared__ int last;
    const int tid = threadIdx.x;
    const int gid = blockIdx.x * 256 + tid;          // 0..12287
    float4 v = ((const float4*)g_sum)[gid];
    double d = (double)v.x + (double)v.y + (double)v.z + (double)v.w;
    #pragma unroll
    for (int off = 16; off > 0; off >>= 1)
        d += __shfl_down_sync(0xffffffffu, d, off);
    if ((tid & 31) == 0) wsum[tid >> 5] = d;
    __syncthreads();
    if (tid < 8) {
        double t = wsum[tid];
        t += __shfl_down_sync(0x000000ffu, t, 4);
        t += __shfl_down_sync(0x000000ffu, t, 2);
        t += __shfl_down_sync(0x000000ffu, t, 1);
        if (tid == 0) {
            g_part[blockIdx.x] = t;
            __threadfence();
            // wrapping inc: returns to 0 after RED_BLOCKS calls (graph-replay safe)
            unsigned old = atomicInc(&g_cnt, RED_BLOCKS - 1);
            last = (old == RED_BLOCKS - 1);
        }
    }
    __syncthreads();
    if (last && tid < 64) {
        double t = (tid < RED_BLOCKS) ? g_part[tid] : 0.0;
        t += __shfl_down_sync(0xffffffffu, t, 16);
        t += __shfl_down_sync(0xffffffffu, t, 8);
        t += __shfl_down_sync(0xffffffffu, t, 4);
        t += __shfl_down_sync(0xffffffffu, t, 2);
        t += __shfl_down_sync(0xffffffffu, t, 1);
        if (tid == 0)  wsum[0] = t;
        if (tid == 32) wsum[1] = t;
        __syncwarp();
        if (tid == 0) out[0] = (float)((wsum[0] + wsum[1]) / (double)BATCH);
    }
}

// ---------------- launch ----------------
extern "C" void kernel_launch(void* const* d_in, const int* in_sizes, int n_in,
                              void* d_out, int out_size) {
    const float* emb  = (const float*)d_in[0];
    const int*   tgt  = (const int*)d_in[1];
    const int*   sids = (const int*)d_in[2];
    const float* W    = (const float*)d_in[3];
    const float* bias = (const float*)d_in[4];
    float*       out  = (float*)d_out;

    cudaFuncSetAttribute(k_gemm, cudaFuncAttributeMaxDynamicSharedMemorySize, SMEM_TOTAL);

    k_pre<<<144, 256>>>(sids, W, bias);
    k_gemm<<<GEMM_CTAS + TRUE_CTAS, 256, SMEM_TOTAL>>>(emb, tgt, W, bias);
    k_red<<<RED_BLOCKS, 256>>>(out);
}

// round 16
// speedup vs baseline: 1.0070x; 1.0070x over previous
#include <cuda_runtime.h>
#include <cuda_bf16.h>
#include <cstdint>

#define BATCH 16384
#define EMBED 256
#define NS    4096
#define VOCAB 50000

// smem: A 4 k-chunks x [128r x 64k bf16] XOR-swizzled = 65536
//       B 3 bufs x [128n x 64k bf16] swizzled = 49152
#define OFF_A   0
#define OFF_B   65536
#define OFF_RED 114688
#define SMEM_TOTAL 115712
#define NCH 64     // (NS/2)/128 n-tiles * 4 k-chunks
#define GEMM_CTAS 256
#define TRUE_CTAS 40
#define TRUE_WARPS (TRUE_CTAS * 8)
#define RED_BLOCKS 48   // 3*BATCH floats / 4 / 256

// ---------------- device scratch ----------------
__device__ __align__(16) __nv_bfloat16 g_Bw[NS * EMBED];
__device__ float g_c[NS];
__device__ __align__(16) float g_sum[3][BATCH];   // [0],[1]: N-halves; [2]: true
__device__ double g_part[RED_BLOCKS];
__device__ unsigned g_cnt;                         // wraps to 0 every replay

__device__ __forceinline__ float neg_log_ec(float fid) {
    const float inv_logv = 1.0f / logf((float)VOCAB + 1.0f);
    float p  = (logf(fid + 2.0f) - logf(fid + 1.0f)) * inv_logv;
    float ec = -expm1f((float)NS * log1pf(-p));
    return -logf(ec);
}

__device__ __forceinline__ unsigned su32(const void* p) {
    return (unsigned)__cvta_generic_to_shared(p);
}

__device__ __forceinline__ uint4 cvt8bf(float4 x, float4 y) {
    __align__(16) __nv_bfloat162 p[4];
    p[0] = __floats2bfloat162_rn(x.x, x.y);
    p[1] = __floats2bfloat162_rn(x.z, x.w);
    p[2] = __floats2bfloat162_rn(y.x, y.y);
    p[3] = __floats2bfloat162_rn(y.z, y.w);
    return *(const uint4*)p;
}

// ---------------- prep: gather B (bf16) + offsets c (round-13 proven) --------
__global__ void k_pre(const int* __restrict__ sids, const float* __restrict__ W,
                      const float* __restrict__ bias) {
    const int b   = blockIdx.x;
    const int tid = threadIdx.x;
    if (b < 512) {
        int i  = b * 256 + tid;
        int s  = i >> 5;
        int d8 = (i & 31) << 3;
        int id = sids[s];
        const float4* src = (const float4*)(W + (size_t)id * EMBED + d8);
        *(uint4*)(g_Bw + (size_t)s * EMBED + d8) = cvt8bf(src[0], src[1]);
    } else {
        int s  = (b - 512) * 256 + tid;
        int id = sids[s];
        g_c[s] = bias[id] + neg_log_ec((float)id);
    }
}

// ---------------- fused GEMM + softplus + shadow true-logits ----------------
__global__ __launch_bounds__(256, 2) void k_gemm(
    const float* __restrict__ emb, const int* __restrict__ tgt,
    const float* __restrict__ W, const float* __restrict__ bias) {
    extern __shared__ __align__(16) char smp[];

    const int tid  = threadIdx.x;
    const int lane = tid & 31;
    const int warp = tid >> 5;

    // ---- shadow CTAs: true logits, hidden under the GEMM ----
    if (blockIdx.x >= GEMM_CTAS) {
        const int gw = (blockIdx.x - GEMM_CTAS) * 8 + warp;
        for (int r0 = gw * 4; r0 < BATCH; r0 += TRUE_WARPS * 4) {
            int ids[4];
            #pragma unroll
            for (int j = 0; j < 4; j++) ids[j] = tgt[r0 + j];
            float s[4];
            #pragma unroll
            for (int j = 0; j < 4; j++) {
                const float4* e4 = (const float4*)(emb + (size_t)(r0 + j) * EMBED);
                const float4* w4 = (const float4*)(W + (size_t)ids[j] * EMBED);
                float4 a0 = e4[lane], a1 = e4[lane + 32];
                float4 b0 = w4[lane], b1 = w4[lane + 32];
                s[j] = a0.x*b0.x + a0.y*b0.y + a0.z*b0.z + a0.w*b0.w
                     + a1.x*b1.x + a1.y*b1.y + a1.z*b1.z + a1.w*b1.w;
            }
            #pragma unroll
            for (int off = 16; off > 0; off >>= 1)
                #pragma unroll
                for (int j = 0; j < 4; j++)
                    s[j] += __shfl_xor_sync(0xffffffffu, s[j], off);
            if (lane == 0) {
                #pragma unroll
                for (int j = 0; j < 4; j++) {
                    float tl = s[j] + bias[ids[j]] + neg_log_ec((float)ids[j]);
                    g_sum[2][r0 + j] = fmaxf(tl, 0.f) - tl + log1pf(expf(-fabsf(tl)));
                }
            }
        }
        return;
    }

    // ---- GEMM CTAs (round-7/10/13 proven path) ----
    const uint32_t base = su32(smp);
    float* red = (float*)(smp + OFF_RED);
    const int wm   = warp & 3;   // 32-row group
    const int wn   = warp >> 2;  // 64-col group
    const int mb   = blockIdx.x >> 1;
    const int half = blockIdx.x & 1;
    const int m0   = mb * 128;
    const int nb0  = half * (NS / 2);

    auto loadB = [&](int ch) {
        const int nt = ch >> 2, kb = ch & 3, b = ch % 3;
        const __nv_bfloat16* sb = g_Bw + (size_t)(nb0 + nt * 128) * EMBED + kb * 64;
        #pragma unroll
        for (int it = 0; it < 4; it++) {
            int q = tid + it * 256;
            int n = q >> 3, g = q & 7;
            uint32_t dst = base + OFF_B + b * 16384 + n * 128 + (((g ^ n) & 7) << 4);
            const void* src = sb + (size_t)n * EMBED + g * 8;
            asm volatile("cp.async.cg.shared.global [%0], [%1], 16;" :: "r"(dst), "l"(src));
        }
        asm volatile("cp.async.commit_group;");
    };

    loadB(0);
    loadB(1);

    #pragma unroll 4
    for (int it = 0; it < 16; it++) {
        int idx = tid + it * 256;
        int r = idx >> 5, G = idx & 31;
        int c = G >> 3, g = G & 7;
        const float4* s = (const float4*)(emb + (size_t)(m0 + r) * EMBED + G * 8);
        float4 x = s[0], y = s[1];
        *(uint4*)(smp + OFF_A + c * 16384 + r * 128 + (((g ^ r) & 7) << 4)) = cvt8bf(x, y);
    }

    float acc[2][8][4];
    #pragma unroll
    for (int mi = 0; mi < 2; mi++)
        #pragma unroll
        for (int ni = 0; ni < 8; ni++)
            #pragma unroll
            for (int q = 0; q < 4; q++) acc[mi][ni][q] = 0.0f;
    float rs[4] = {0.f, 0.f, 0.f, 0.f};

    auto ldA = [&](unsigned (&a)[2][4], uint32_t abase, int kk) {
        #pragma unroll
        for (int mi = 0; mi < 2; mi++) {
            int rr = wm * 32 + mi * 16 + (lane & 15);
            int gp = (kk >> 3) + (lane >> 4);
            unsigned addr = abase + rr * 128 + (((gp ^ rr) & 7) << 4);
            asm volatile("ldmatrix.sync.aligned.m8n8.x4.shared.b16 {%0,%1,%2,%3}, [%4];\n"
                : "=r"(a[mi][0]), "=r"(a[mi][1]), "=r"(a[mi][2]), "=r"(a[mi][3])
                : "r"(addr));
        }
    };
    auto ldBf = [&](unsigned (&b)[8][2], uint32_t bbase, int kk) {
        #pragma unroll
        for (int np = 0; np < 4; np++) {
            int nn = wn * 64 + np * 16 + ((lane >> 4) << 3) + (lane & 7);
            int gp = (kk >> 3) + ((lane >> 3) & 1);
            unsigned addr = bbase + nn * 128 + (((gp ^ nn) & 7) << 4);
            asm volatile("ldmatrix.sync.aligned.m8n8.x4.shared.b16 {%0,%1,%2,%3}, [%4];\n"
                : "=r"(b[np * 2][0]), "=r"(b[np * 2][1]),
                  "=r"(b[np * 2 + 1][0]), "=r"(b[np * 2 + 1][1])
                : "r"(addr));
        }
    };

    for (int ch = 0; ch < NCH; ch++) {
        if (ch < NCH - 1) asm volatile("cp.async.wait_group 1;");
        else              asm volatile("cp.async.wait_group 0;");
        __syncthreads();
        if (ch + 2 < NCH) loadB(ch + 2);

        const int kb = ch & 3;
        const uint32_t abase = base + OFF_A + kb * 16384;
        const uint32_t bbase = base + OFF_B + (ch % 3) * 16384;

        unsigned aF[2][2][4];
        unsigned bF[8][2];
        ldA(aF[0], abase, 0);

        #pragma unroll
        for (int ki = 0; ki < 4; ki++) {
            ldBf(bF, bbase, ki * 16);
            if (ki < 3) ldA(aF[(ki + 1) & 1], abase, (ki + 1) * 16);
            unsigned (&a)[2][4] = aF[ki & 1];
            #pragma unroll
            for (int mi = 0; mi < 2; mi++)
                #pragma unroll
                for (int ni = 0; ni < 8; ni++)
                    asm volatile(
                        "mma.sync.aligned.m16n8k16.row.col.f32.bf16.bf16.f32 "
                        "{%0,%1,%2,%3},{%4,%5,%6,%7},{%8,%9},{%0,%1,%2,%3};\n"
                        : "+f"(acc[mi][ni][0]), "+f"(acc[mi][ni][1]),
                          "+f"(acc[mi][ni][2]), "+f"(acc[mi][ni][3])
                        : "r"(a[mi][0]), "r"(a[mi][1]), "r"(a[mi][2]), "r"(a[mi][3]),
                          "r"(bF[ni][0]), "r"(bF[ni][1]));
        }

        if (kb == 3) {
            const int nt = ch >> 2;
            const float* cp = g_c + nb0 + nt * 128 + wn * 64 + (lane & 3) * 2;
            #pragma unroll
            for (int mi = 0; mi < 2; mi++) {
                float lin0 = 0.f, lin1 = 0.f, pr0 = 1.f, pr1 = 1.f;
                #pragma unroll
                for (int ni = 0; ni < 8; ni++) {
                    float2 cf = *(const float2*)(cp + ni * 8);
                    float l0 = acc[mi][ni][0] + cf.x;
                    float l1 = acc[mi][ni][1] + cf.y;
                    float l2 = acc[mi][ni][2] + cf.x;
                    float l3 = acc[mi][ni][3] + cf.y;
                    lin0 += fmaxf(l0, 0.f) + fmaxf(l1, 0.f);
                    lin1 += fmaxf(l2, 0.f) + fmaxf(l3, 0.f);
                    pr0 *= (1.f + __expf(-fabsf(l0))) * (1.f + __expf(-fabsf(l1)));
                    pr1 *= (1.f + __expf(-fabsf(l2))) * (1.f + __expf(-fabsf(l3)));
                    acc[mi][ni][0] = 0.f; acc[mi][ni][1] = 0.f;
                    acc[mi][ni][2] = 0.f; acc[mi][ni][3] = 0.f;
                }
                rs[mi * 2 + 0] += lin0 + __logf(pr0);
                rs[mi * 2 + 1] += lin1 + __logf(pr1);
            }
        }
    }

    // ---- row-sum reduction ----
    #pragma unroll
    for (int s = 0; s < 4; s++) {
        rs[s] += __shfl_xor_sync(0xffffffffu, rs[s], 1);
        rs[s] += __shfl_xor_sync(0xffffffffu, rs[s], 2);
    }
    __syncthreads();
    if ((lane & 3) == 0) {
        #pragma unroll
        for (int s = 0; s < 4; s++) {
            int mi = s >> 1, hi = s & 1;
            int row = wm * 32 + mi * 16 + hi * 8 + (lane >> 2);
            red[wn * 128 + row] = rs[s];
        }
    }
    __syncthreads();
    if (tid < 128)
        g_sum[half][m0 + tid] = red[tid] + red[128 + tid];
}

// ---------------- fused reduction: 48 blocks; last block writes the mean ----
// Blocks retire freely (no residency assumption); wrapping atomicInc resets
// the counter every replay; final sum runs in a single warp (deterministic).
__global__ void k_red(float* __restrict__ out) {
    __shared__ double wsum[8];
    __shared__ int last;
    const int tid = threadIdx.x;
    const int gid = blockIdx.x * 256 + tid;          // 0..12287
    float4 v = ((const float4*)g_sum)[gid];
    double d = (double)v.x + (double)v.y + (double)v.z + (double)v.w;
    #pragma unroll
    for (int off = 16; off > 0; off >>= 1)
        d += __shfl_down_sync(0xffffffffu, d, off);
    if ((tid & 31) == 0) wsum[tid >> 5] = d;
    __syncthreads();
    if (tid < 8) {
        double t = wsum[tid];
        t += __shfl_down_sync(0x000000ffu, t, 4);
        t += __shfl_down_sync(0x000000ffu, t, 2);
        t += __shfl_down_sync(0x000000ffu, t, 1);
        if (tid == 0) {
            g_part[blockIdx.x] = t;
            __threadfence();
            unsigned old = atomicInc(&g_cnt, RED_BLOCKS - 1);  // wraps each replay
            last = (old == RED_BLOCKS - 1);
        }
    }
    __syncthreads();
    if (last && tid < 32) {
        double t = g_part[tid] + g_part[tid + 16];   // 48 = 32 + 16: lanes 0-15 add tail
        // note: lanes 16-31 add g_part[32..47]; lanes 0-15 double-count? -> use exact split:
        t = g_part[tid] + ((tid < 16) ? g_part[tid + 32] : 0.0);
        t += __shfl_down_sync(0xffffffffu, t, 16);
        t += __shfl_down_sync(0xffffffffu, t, 8);
        t += __shfl_down_sync(0xffffffffu, t, 4);
        t += __shfl_down_sync(0xffffffffu, t, 2);
        t += __shfl_down_sync(0xffffffffu, t, 1);
        if (tid == 0) out[0] = (float)(t / (double)BATCH);
    }
}

// ---------------- launch ----------------
extern "C" void kernel_launch(void* const* d_in, const int* in_sizes, int n_in,
                              void* d_out, int out_size) {
    const float* emb  = (const float*)d_in[0];
    const int*   tgt  = (const int*)d_in[1];
    const int*   sids = (const int*)d_in[2];
    const float* W    = (const float*)d_in[3];
    const float* bias = (const float*)d_in[4];
    float*       out  = (float*)d_out;

    cudaFuncSetAttribute(k_gemm, cudaFuncAttributeMaxDynamicSharedMemorySize, SMEM_TOTAL);

    k_pre<<<528, 256>>>(sids, W, bias);
    k_gemm<<<GEMM_CTAS + TRUE_CTAS, 256, SMEM_TOTAL>>>(emb, tgt, W, bias);
    k_red<<<RED_BLOCKS, 256>>>(out);
}